// round 5
// baseline (speedup 1.0000x reference)
#include <cuda_runtime.h>
#include <stdint.h>

#define NMAX 262144
#define NMASK (NMAX - 1)
#define EMAX (NMAX * 32)

#define C_DT  0.002f
#define C_DT2 (0.002f * 0.002f)
// 30/pi / h^3, h = 0.05
#define SPIKY_OVER_H3 76394.37268410977f

// Scratch (device globals; no allocation anywhere)
__device__ __align__(32) float4 g_node[2 * NMAX];   // {aA, c2, mass, p} {vx, vy, ax, ay}
__device__ __align__(16) float  g_scr[NMAX * 12];   // 9 accumulators + 3 pad (48B/node)

// ---------------------------------------------------------------------------
// Kernel 1: pack per-node gather struct, zero scratch
// ---------------------------------------------------------------------------
__global__ void k_setup(const float* __restrict__ area,
                        const float* __restrict__ aA,
                        const float* __restrict__ rd,
                        const float* __restrict__ dens,
                        const float* __restrict__ pres,
                        const float2* __restrict__ vel,
                        const float2* __restrict__ acc,
                        int n)
{
    int t = blockIdx.x * blockDim.x + threadIdx.x;
    if (t >= n) return;
    float a  = area[t];
    float aa = aA[t];
    float r  = rd[t];
    float mass = a * r;
    float c2   = aa * aa / mass;
    float dr   = dens[t] * r;
    float p    = pres[t] / (dr * dr);
    float2 v  = vel[t];
    float2 ac = acc[t];
    g_node[2 * t]     = make_float4(aa, c2, mass, p);
    g_node[2 * t + 1] = make_float4(v.x, v.y, ac.x, ac.y);

    float4* s = reinterpret_cast<float4*>(&g_scr[12 * t]);
    float4 z = make_float4(0.f, 0.f, 0.f, 0.f);
    s[0] = z; s[1] = z; s[2] = z;
}

// ---------------------------------------------------------------------------
// Kernel 2: edge scatter, 4 edges/thread, fully vectorized loads (int32 nb).
// slots: 0:kSum1x 1:kSum1y 2:kSum2 3:sum aA_j*(v_j.grad)
//        4:sum aA_j*(a_j.grad) 5:sum m_j*gx 6:sum m_j*gy
//        7:sum m_j*p_j*gx 8:sum m_j*p_j*gy
// ---------------------------------------------------------------------------
__device__ __forceinline__ void edge_body(int i, int j, float q, float dx, float dy)
{
    float t = fmaxf(1.0f - q, 0.0f);
    float mag = -SPIKY_OVER_H3 * t * t;
    float gx = mag * dx;
    float gy = mag * dy;
    float g2 = gx * gx + gy * gy;

    float4 c0 = g_node[2 * j];       // {aA, c2, mass, p}
    float4 c1 = g_node[2 * j + 1];   // {vx, vy, ax, ay}

    float A0 = c0.x * gx;
    float A1 = c0.x * gy;
    float A2 = c0.y * g2;
    float A3 = c0.x * (c1.x * gx + c1.y * gy);
    float A4 = c0.x * (c1.z * gx + c1.w * gy);
    float A5 = c0.z * gx;
    float A6 = c0.z * gy;
    float wp = c0.z * c0.w;
    float A7 = wp * gx;
    float A8 = wp * gy;

    float* base = &g_scr[12 * i];
    asm volatile("red.global.add.v4.f32 [%0], {%1,%2,%3,%4};"
                 :: "l"(base), "f"(A0), "f"(A1), "f"(A2), "f"(A3) : "memory");
    asm volatile("red.global.add.v4.f32 [%0], {%1,%2,%3,%4};"
                 :: "l"(base + 4), "f"(A4), "f"(A5), "f"(A6), "f"(A7) : "memory");
    atomicAdd(base + 8, A8);
}

__global__ void k_edges(const int* __restrict__ nb,
                        const float* __restrict__ radial,
                        const float2* __restrict__ dir,
                        int E)
{
    int e4 = (blockIdx.x * blockDim.x + threadIdx.x) * 4;
    if (e4 >= E) return;

    if (e4 + 3 < E) {
        int4   ii = *reinterpret_cast<const int4*>(nb + e4);
        int4   jj = *reinterpret_cast<const int4*>(nb + E + e4);
        float4 qq = *reinterpret_cast<const float4*>(radial + e4);
        float4 d0 = *reinterpret_cast<const float4*>(dir + e4);        // edges 0,1
        float4 d1 = *reinterpret_cast<const float4*>(dir + e4 + 2);    // edges 2,3

        edge_body(ii.x & NMASK, jj.x & NMASK, qq.x, d0.x, d0.y);
        edge_body(ii.y & NMASK, jj.y & NMASK, qq.y, d0.z, d0.w);
        edge_body(ii.z & NMASK, jj.z & NMASK, qq.z, d1.x, d1.y);
        edge_body(ii.w & NMASK, jj.w & NMASK, qq.w, d1.z, d1.w);
    } else {
        for (int e = e4; e < E; e++) {
            int i = nb[e] & NMASK;
            int j = nb[E + e] & NMASK;
            float2 d = dir[e];
            edge_body(i, j, radial[e], d.x, d.y);
        }
    }
}

// ---------------------------------------------------------------------------
// Kernel 3: finalize alpha + recombine i-side factored terms, pack [N,5]
// ---------------------------------------------------------------------------
__global__ void k_final(const float* __restrict__ area,
                        const float* __restrict__ aA,
                        const float* __restrict__ rd,
                        const float* __restrict__ dens,
                        const float* __restrict__ pres,
                        const float2* __restrict__ vel,
                        const float2* __restrict__ acc,
                        float* __restrict__ out,
                        int n)
{
    int t = blockIdx.x * blockDim.x + threadIdx.x;
    if (t >= n) return;

    const float4* s4 = reinterpret_cast<const float4*>(&g_scr[12 * t]);
    float4 sa = s4[0];               // {kSum1x, kSum1y, kSum2, s_v}
    float4 sb = s4[1];               // {s_a, m_gx, m_gy, mp_gx}
    float  s8 = g_scr[12 * t + 8];   // mp_gy

    float a  = area[t];
    float aa = aA[t];
    float r  = rd[t];
    float mass = a * r;
    float fac  = -C_DT2 * aa;

    float alpha = fac / mass * (sa.x * sa.x + sa.y * sa.y) + fac * sa.z;
    alpha = fminf(fmaxf(alpha, -1.0f), -1e-7f);

    float2 v  = vel[t];
    float2 ac = acc[t];
    float dr  = dens[t] * r;
    float p   = pres[t] / (dr * dr);

    float source = -C_DT * (v.x * sa.x + v.y * sa.y) + C_DT * sa.w;
    float ksum   =  C_DT2 * (ac.x * sa.x + ac.y * sa.y) - C_DT2 * sb.x;
    float ax = -p * sb.y - sb.w;
    float ay = -p * sb.z - s8;

    out[5 * t + 0] = alpha;
    out[5 * t + 1] = source;
    out[5 * t + 2] = ax;
    out[5 * t + 3] = ay;
    out[5 * t + 4] = ksum;
}

// ---------------------------------------------------------------------------
extern "C" void kernel_launch(void* const* d_in, const int* in_sizes, int n_in,
                              void* d_out, int out_size)
{
    // Detect input ordering from in_sizes (element counts identical for
    // int32/int64 neighbors, so dtype doesn't affect detection).
    //   dict order:  [N, N, N, N, N, 2N, 2N, E, 2E, 2E]
    //   alpha order: [N, N, N, 2E, 2E, 2N, 2N, N, E, N]
    int idx_area, idx_aA, idx_rest, idx_dens, idx_pres,
        idx_vel, idx_acc, idx_radial, idx_dir, idx_nb;

    if (in_sizes[3] == in_sizes[0]) {
        // dict / insertion order
        idx_area = 0; idx_aA = 1; idx_rest = 2; idx_dens = 3; idx_pres = 4;
        idx_vel = 5; idx_acc = 6; idx_radial = 7; idx_dir = 8; idx_nb = 9;
    } else {
        // alphabetical: fluidActualArea, fluidArea, fluidDensity, fluidDistances,
        //               fluidNeighbors, fluidPredAccel, fluidPredictedVelocity,
        //               fluidPressure2, fluidRadialDistances, fluidRestDensity
        idx_aA = 0; idx_area = 1; idx_dens = 2; idx_dir = 3; idx_nb = 4;
        idx_acc = 5; idx_vel = 6; idx_pres = 7; idx_radial = 8; idx_rest = 9;
    }

    const float*  area   = (const float*)d_in[idx_area];
    const float*  aA     = (const float*)d_in[idx_aA];
    const float*  rd     = (const float*)d_in[idx_rest];
    const float*  dens   = (const float*)d_in[idx_dens];
    const float*  pres   = (const float*)d_in[idx_pres];
    const float2* vel    = (const float2*)d_in[idx_vel];
    const float2* acc    = (const float2*)d_in[idx_acc];
    const float*  radial = (const float*)d_in[idx_radial];
    const float2* dir    = (const float2*)d_in[idx_dir];
    const int*    nb     = (const int*)d_in[idx_nb];   // JAX x64 disabled -> int32
    float* out = (float*)d_out;

    int n = in_sizes[idx_area];
    int E = in_sizes[idx_radial];
    if (n > NMAX) n = NMAX;
    if (E > EMAX) E = EMAX;

    const int TPB = 256;
    k_setup<<<(n + TPB - 1) / TPB, TPB>>>(area, aA, rd, dens, pres, vel, acc, n);
    int nthr = (E + 3) / 4;
    k_edges<<<(nthr + TPB - 1) / TPB, TPB>>>(nb, radial, dir, E);
    k_final<<<(n + TPB - 1) / TPB, TPB>>>(area, aA, rd, dens, pres, vel, acc, out, n);
}

// round 6
// speedup vs baseline: 1.0436x; 1.0436x over previous
#include <cuda_runtime.h>
#include <stdint.h>

#define NMAX 262144
#define NMASK (NMAX - 1)
#define EMAX (NMAX * 32)

#define C_DT  0.002f
#define C_DT2 (0.002f * 0.002f)
// 30/pi / h^3, h = 0.05
#define SPIKY_OVER_H3 76394.37268410977f

// Scratch (device globals; no allocation anywhere)
__device__ __align__(32) float4 g_node[2 * NMAX];   // {aA, c2, mass, p} {vx, vy, ax, ay}
__device__ float  g_p[NMAX];                        // p_i for in-edge accel fuse
__device__ __align__(16) float4 g_scrA[NMAX];       // {kSum1x, kSum1y, kSum2, s_v}
__device__ __align__(16) float4 g_scrB[NMAX];       // {s_a, accx, accy, pad}

// ---------------------------------------------------------------------------
// Kernel 1: pack per-node gather struct, zero scratch planes
// ---------------------------------------------------------------------------
__global__ void k_setup(const float* __restrict__ area,
                        const float* __restrict__ aA,
                        const float* __restrict__ rd,
                        const float* __restrict__ dens,
                        const float* __restrict__ pres,
                        const float2* __restrict__ vel,
                        const float2* __restrict__ acc,
                        int n)
{
    int t = blockIdx.x * blockDim.x + threadIdx.x;
    if (t >= n) return;
    float a  = area[t];
    float aa = aA[t];
    float r  = rd[t];
    float mass = a * r;
    float c2   = aa * aa / mass;
    float dr   = dens[t] * r;
    float p    = pres[t] / (dr * dr);
    float2 v  = vel[t];
    float2 ac = acc[t];
    g_node[2 * t]     = make_float4(aa, c2, mass, p);
    g_node[2 * t + 1] = make_float4(v.x, v.y, ac.x, ac.y);
    g_p[t] = p;

    float4 z = make_float4(0.f, 0.f, 0.f, 0.f);
    g_scrA[t] = z;
    g_scrB[t] = z;
}

// ---------------------------------------------------------------------------
// Kernel 2: edge scatter, 4 edges/thread, vectorized loads, EXACTLY 2 red.v4
// per edge (7 live accumulator slots + 1 zero pad).
//   plane A: {Σ aA_j·gx, Σ aA_j·gy, Σ c2_j·g2, Σ aA_j·(v_j·g)}
//   plane B: {Σ aA_j·(a_j·g), Σ m_j·(p_i+p_j)·gx, Σ m_j·(p_i+p_j)·gy, 0}
// ---------------------------------------------------------------------------
__device__ __forceinline__ void edge_body(int i, int j, float q, float dx, float dy)
{
    float t = fmaxf(1.0f - q, 0.0f);
    float mag = -SPIKY_OVER_H3 * t * t;
    float gx = mag * dx;
    float gy = mag * dy;
    float g2 = gx * gx + gy * gy;

    float4 c0 = g_node[2 * j];       // {aA, c2, mass, p}
    float4 c1 = g_node[2 * j + 1];   // {vx, vy, ax, ay}
    float  pi = g_p[i];

    float A0 = c0.x * gx;
    float A1 = c0.x * gy;
    float A2 = c0.y * g2;
    float A3 = c0.x * (c1.x * gx + c1.y * gy);

    float B0 = c0.x * (c1.z * gx + c1.w * gy);
    float w  = c0.z * (pi + c0.w);   // m_j * (p_i + p_j)
    float B1 = w * gx;
    float B2 = w * gy;

    asm volatile("red.global.add.v4.f32 [%0], {%1,%2,%3,%4};"
                 :: "l"(&g_scrA[i]), "f"(A0), "f"(A1), "f"(A2), "f"(A3) : "memory");
    asm volatile("red.global.add.v4.f32 [%0], {%1,%2,%3,%4};"
                 :: "l"(&g_scrB[i]), "f"(B0), "f"(B1), "f"(B2), "f"(0.0f) : "memory");
}

__global__ void k_edges(const int* __restrict__ nb,
                        const float* __restrict__ radial,
                        const float2* __restrict__ dir,
                        int E)
{
    int e4 = (blockIdx.x * blockDim.x + threadIdx.x) * 4;
    if (e4 >= E) return;

    if (e4 + 3 < E) {
        int4   ii = *reinterpret_cast<const int4*>(nb + e4);
        int4   jj = *reinterpret_cast<const int4*>(nb + E + e4);
        float4 qq = *reinterpret_cast<const float4*>(radial + e4);
        float4 d0 = *reinterpret_cast<const float4*>(dir + e4);        // edges 0,1
        float4 d1 = *reinterpret_cast<const float4*>(dir + e4 + 2);    // edges 2,3

        edge_body(ii.x & NMASK, jj.x & NMASK, qq.x, d0.x, d0.y);
        edge_body(ii.y & NMASK, jj.y & NMASK, qq.y, d0.z, d0.w);
        edge_body(ii.z & NMASK, jj.z & NMASK, qq.z, d1.x, d1.y);
        edge_body(ii.w & NMASK, jj.w & NMASK, qq.w, d1.z, d1.w);
    } else {
        for (int e = e4; e < E; e++) {
            int i = nb[e] & NMASK;
            int j = nb[E + e] & NMASK;
            float2 d = dir[e];
            edge_body(i, j, radial[e], d.x, d.y);
        }
    }
}

// ---------------------------------------------------------------------------
// Kernel 3: finalize alpha + recombine factored i-side terms, pack [N,5]
// ---------------------------------------------------------------------------
__global__ void k_final(const float* __restrict__ area,
                        const float* __restrict__ aA,
                        const float* __restrict__ rd,
                        const float2* __restrict__ vel,
                        const float2* __restrict__ acc,
                        float* __restrict__ out,
                        int n)
{
    int t = blockIdx.x * blockDim.x + threadIdx.x;
    if (t >= n) return;

    float4 sa = g_scrA[t];           // {kSum1x, kSum1y, kSum2, s_v}
    float4 sb = g_scrB[t];           // {s_a, accx, accy, pad}

    float a  = area[t];
    float aa = aA[t];
    float r  = rd[t];
    float mass = a * r;
    float fac  = -C_DT2 * aa;

    float alpha = fac / mass * (sa.x * sa.x + sa.y * sa.y) + fac * sa.z;
    alpha = fminf(fmaxf(alpha, -1.0f), -1e-7f);

    float2 v  = vel[t];
    float2 ac = acc[t];

    float source = -C_DT * (v.x * sa.x + v.y * sa.y) + C_DT * sa.w;
    float ksum   =  C_DT2 * (ac.x * sa.x + ac.y * sa.y) - C_DT2 * sb.x;
    float ax = -sb.y;
    float ay = -sb.z;

    out[5 * t + 0] = alpha;
    out[5 * t + 1] = source;
    out[5 * t + 2] = ax;
    out[5 * t + 3] = ay;
    out[5 * t + 4] = ksum;
}

// ---------------------------------------------------------------------------
extern "C" void kernel_launch(void* const* d_in, const int* in_sizes, int n_in,
                              void* d_out, int out_size)
{
    // Detect input ordering from in_sizes.
    //   dict order:  [N, N, N, N, N, 2N, 2N, E, 2E, 2E]
    //   alpha order: [N, N, N, 2E, 2E, 2N, 2N, N, E, N]
    int idx_area, idx_aA, idx_rest, idx_dens, idx_pres,
        idx_vel, idx_acc, idx_radial, idx_dir, idx_nb;

    if (in_sizes[3] == in_sizes[0]) {
        idx_area = 0; idx_aA = 1; idx_rest = 2; idx_dens = 3; idx_pres = 4;
        idx_vel = 5; idx_acc = 6; idx_radial = 7; idx_dir = 8; idx_nb = 9;
    } else {
        idx_aA = 0; idx_area = 1; idx_dens = 2; idx_dir = 3; idx_nb = 4;
        idx_acc = 5; idx_vel = 6; idx_pres = 7; idx_radial = 8; idx_rest = 9;
    }

    const float*  area   = (const float*)d_in[idx_area];
    const float*  aA     = (const float*)d_in[idx_aA];
    const float*  rd     = (const float*)d_in[idx_rest];
    const float*  dens   = (const float*)d_in[idx_dens];
    const float*  pres   = (const float*)d_in[idx_pres];
    const float2* vel    = (const float2*)d_in[idx_vel];
    const float2* acc    = (const float2*)d_in[idx_acc];
    const float*  radial = (const float*)d_in[idx_radial];
    const float2* dir    = (const float2*)d_in[idx_dir];
    const int*    nb     = (const int*)d_in[idx_nb];   // int32 (JAX x64 disabled)
    float* out = (float*)d_out;

    int n = in_sizes[idx_area];
    int E = in_sizes[idx_radial];
    if (n > NMAX) n = NMAX;
    if (E > EMAX) E = EMAX;

    const int TPB = 256;
    k_setup<<<(n + TPB - 1) / TPB, TPB>>>(area, aA, rd, dens, pres, vel, acc, n);
    int nthr = (E + 3) / 4;
    k_edges<<<(nthr + TPB - 1) / TPB, TPB>>>(nb, radial, dir, E);
    k_final<<<(n + TPB - 1) / TPB, TPB>>>(area, aA, rd, vel, acc, out, n);
}